// round 2
// baseline (speedup 1.0000x reference)
#include <cuda_runtime.h>

#define B_   32
#define C1   1024
#define C2   256
#define C3   64
#define T_   2048
#define EPSV 1e-5f
#define MUHALF ((size_t)B_ * 32 * T_)

typedef unsigned long long u64;

// Scratch (allocation-free: __device__ globals)
__device__ float g_h[(size_t)B_ * C2 * T_];     // 64 MB intermediate h = relu(conv1(bn1(x)))
__device__ float g_a1[C1], g_d1[C1];
__device__ float g_w1f[C2 * C1], g_b1f[C2];
__device__ float g_a2[C2], g_d2[C2];
__device__ float g_w2f[C3 * C2], g_b2f[C3];

// ---------------- packed f32x2 helpers (FFMA2: 2x fp32 FMA rate, PTX-only) --
__device__ __forceinline__ u64 fma2(u64 a, u64 b, u64 c) {
    u64 r; asm("fma.rn.f32x2 %0, %1, %2, %3;" : "=l"(r) : "l"(a), "l"(b), "l"(c)); return r;
}
__device__ __forceinline__ u64 pack2(float x) {
    u64 r; asm("mov.b64 %0, {%1, %1};" : "=l"(r) : "f"(x)); return r;
}
__device__ __forceinline__ void unpack2(u64 p, float& lo, float& hi) {
    asm("mov.b64 {%0, %1}, %2;" : "=f"(lo), "=f"(hi) : "l"(p));
}

// ---------------- per-channel BN stats -> folded scale/shift ----------------
// a[c] = gamma*rsqrt(var+eps),  d[c] = beta - mean*a
__device__ __forceinline__ void stats_body(const float* __restrict__ src, int C,
    const float* __restrict__ gamma, const float* __restrict__ beta,
    float* __restrict__ a_out, float* __restrict__ d_out)
{
    __shared__ float sh_s[256], sh_q[256];
    const int c = blockIdx.x, tid = threadIdx.x;
    float s = 0.f, q = 0.f;
    for (int b = 0; b < B_; b++) {
        const float4* row = (const float4*)(src + ((size_t)b * C + c) * T_);
        #pragma unroll
        for (int i = 0; i < T_ / 4 / 256; i++) {
            float4 v = row[tid + i * 256];
            s += v.x + v.y + v.z + v.w;
            q += v.x*v.x + v.y*v.y + v.z*v.z + v.w*v.w;
        }
    }
    sh_s[tid] = s; sh_q[tid] = q;
    __syncthreads();
    for (int off = 128; off > 0; off >>= 1) {
        if (tid < off) { sh_s[tid] += sh_s[tid + off]; sh_q[tid] += sh_q[tid + off]; }
        __syncthreads();
    }
    if (tid == 0) {
        const float inv_n = 1.f / (float)(B_ * T_);
        float mean = sh_s[0] * inv_n;
        float var  = sh_q[0] * inv_n - mean * mean;
        float a = gamma[c] * rsqrtf(var + EPSV);
        a_out[c] = a;
        d_out[c] = beta[c] - mean * a;
    }
}

__global__ void stats1_kernel(const float* __restrict__ x,
                              const float* __restrict__ g, const float* __restrict__ b) {
    stats_body(x, C1, g, b, g_a1, g_d1);
}
__global__ void stats2_kernel(const float* __restrict__ g, const float* __restrict__ b) {
    stats_body(g_h, C2, g, b, g_a2, g_d2);
}

// ---------------- fold BN into conv weight/bias ------------------------------
// wf[o,c] = w[o,c]*a[c];  bf[o] = bias[o] + sum_c w[o,c]*d[c]
__device__ __forceinline__ void fold_body(const float* __restrict__ w, const float* __restrict__ bias,
    const float* __restrict__ a, const float* __restrict__ d, int K,
    float* __restrict__ wf, float* __restrict__ bf)
{
    __shared__ float sh[256];
    const int o = blockIdx.x, tid = threadIdx.x;
    float acc = 0.f;
    for (int c = tid; c < K; c += 256) {
        float wv = w[(size_t)o * K + c];
        wf[(size_t)o * K + c] = wv * a[c];
        acc += wv * d[c];
    }
    sh[tid] = acc;
    __syncthreads();
    for (int off = 128; off > 0; off >>= 1) {
        if (tid < off) sh[tid] += sh[tid + off];
        __syncthreads();
    }
    if (tid == 0) bf[o] = bias[o] + sh[0];
}

__global__ void fold1_kernel(const float* __restrict__ w, const float* __restrict__ b) {
    fold_body(w, b, g_a1, g_d1, C1, g_w1f, g_b1f);
}
__global__ void fold2_kernel(const float* __restrict__ w, const float* __restrict__ b) {
    fold_body(w, b, g_a2, g_d2, C2, g_w2f, g_b2f);
}

// ---------------- GEMM1: h[b] = relu(W1f(256x1024) @ X[b](1024x2048) + b1f) --
// 128x128 tile, BK=8, 256 threads, 8x8 microtile packed into 8x4 f32x2 accs.
__global__ __launch_bounds__(256) void gemm1_kernel(const float* __restrict__ x) {
    __shared__ float As[8][128];   // As[k][m] (W transposed)
    __shared__ float Bs[8][128];   // Bs[k][n]
    const int b  = blockIdx.z;
    const int m0 = blockIdx.y * 128;
    const int n0 = blockIdx.x * 128;
    const int tid = threadIdx.x;
    const int tx = tid & 15, ty = tid >> 4;
    const float* X = x + (size_t)b * C1 * T_;

    u64 acc[8][4];
    #pragma unroll
    for (int i = 0; i < 8; i++)
        #pragma unroll
        for (int j = 0; j < 4; j++) acc[i][j] = 0ull;

    const int arow = tid >> 1, acol = (tid & 1) * 4;
    const int brow = tid >> 5, bcol = (tid & 31) * 4;
    const float* aptr = g_w1f + (size_t)(m0 + arow) * C1 + acol;
    const float* bptr = X + (size_t)brow * T_ + n0 + bcol;

    for (int k0 = 0; k0 < C1; k0 += 8) {
        float4 av = *(const float4*)(aptr + k0);
        float4 bv = *(const float4*)(bptr + (size_t)k0 * T_);
        __syncthreads();
        As[acol + 0][arow] = av.x;
        As[acol + 1][arow] = av.y;
        As[acol + 2][arow] = av.z;
        As[acol + 3][arow] = av.w;
        *(float4*)&Bs[brow][bcol] = bv;
        __syncthreads();
        #pragma unroll
        for (int k = 0; k < 8; k++) {
            float4 a0 = *(const float4*)&As[k][ty * 8];
            float4 a1 = *(const float4*)&As[k][ty * 8 + 4];
            const u64* bp = (const u64*)&Bs[k][tx * 8];
            u64 b0 = bp[0], b1 = bp[1], b2 = bp[2], b3 = bp[3];
            float ar[8] = {a0.x, a0.y, a0.z, a0.w, a1.x, a1.y, a1.z, a1.w};
            #pragma unroll
            for (int i = 0; i < 8; i++) {
                u64 A = pack2(ar[i]);
                acc[i][0] = fma2(A, b0, acc[i][0]);
                acc[i][1] = fma2(A, b1, acc[i][1]);
                acc[i][2] = fma2(A, b2, acc[i][2]);
                acc[i][3] = fma2(A, b3, acc[i][3]);
            }
        }
    }

    float* H = g_h + (size_t)b * C2 * T_;
    #pragma unroll
    for (int i = 0; i < 8; i++) {
        const int row = m0 + ty * 8 + i;
        const float bias = g_b1f[row];
        float v[8];
        #pragma unroll
        for (int j = 0; j < 4; j++) unpack2(acc[i][j], v[2*j], v[2*j+1]);
        float4 o0, o1;
        o0.x = fmaxf(v[0] + bias, 0.f); o0.y = fmaxf(v[1] + bias, 0.f);
        o0.z = fmaxf(v[2] + bias, 0.f); o0.w = fmaxf(v[3] + bias, 0.f);
        o1.x = fmaxf(v[4] + bias, 0.f); o1.y = fmaxf(v[5] + bias, 0.f);
        o1.z = fmaxf(v[6] + bias, 0.f); o1.w = fmaxf(v[7] + bias, 0.f);
        *(float4*)(H + (size_t)row * T_ + n0 + tx * 8)     = o0;
        *(float4*)(H + (size_t)row * T_ + n0 + tx * 8 + 4) = o1;
    }
}

// ---------------- GEMM2: out[b] = W2f(64x256) @ h[b](256x2048) + b2f, split --
// 64x64 tile, BK=8, 256 threads, 4x4 microtile -> 4x2 f32x2 accs.
__global__ __launch_bounds__(256) void gemm2_kernel(float* __restrict__ out) {
    __shared__ float As[8][64];
    __shared__ float Bs[8][64];
    const int b  = blockIdx.z;
    const int n0 = blockIdx.x * 64;
    const int tid = threadIdx.x;
    const int tx = tid & 15, ty = tid >> 4;
    const float* H = g_h + (size_t)b * C2 * T_;

    u64 acc[4][2];
    #pragma unroll
    for (int i = 0; i < 4; i++) { acc[i][0] = 0ull; acc[i][1] = 0ull; }

    const int arow = tid >> 2, acol = (tid & 3) * 2;
    const int brow = tid >> 5, bcol = (tid & 31) * 2;

    for (int k0 = 0; k0 < C2; k0 += 8) {
        float2 av = *(const float2*)(g_w2f + (size_t)arow * C2 + k0 + acol);
        float2 bv = *(const float2*)(H + (size_t)(k0 + brow) * T_ + n0 + bcol);
        __syncthreads();
        As[acol + 0][arow] = av.x;
        As[acol + 1][arow] = av.y;
        *(float2*)&Bs[brow][bcol] = bv;
        __syncthreads();
        #pragma unroll
        for (int k = 0; k < 8; k++) {
            float4 a = *(const float4*)&As[k][ty * 4];
            const u64* bp = (const u64*)&Bs[k][tx * 4];
            u64 b0 = bp[0], b1 = bp[1];
            float ar[4] = {a.x, a.y, a.z, a.w};
            #pragma unroll
            for (int i = 0; i < 4; i++) {
                u64 A = pack2(ar[i]);
                acc[i][0] = fma2(A, b0, acc[i][0]);
                acc[i][1] = fma2(A, b1, acc[i][1]);
            }
        }
    }

    // epilogue: bias + mu/logvar split:
    // o <  32 -> mu[b, o, t]      at  b*32*T + o*T + t
    // o >= 32 -> logvar[b,o-32,t] at  MUHALF + b*32*T + (o-32)*T + t
    #pragma unroll
    for (int i = 0; i < 4; i++) {
        const int o = ty * 4 + i;
        const float bias = g_b2f[o];
        const size_t base = (o < 32)
            ? ((size_t)b * 32 * T_ + (size_t)o * T_)
            : (MUHALF + (size_t)b * 32 * T_ + (size_t)(o - 32) * T_);
        #pragma unroll
        for (int j = 0; j < 2; j++) {
            float lo, hi; unpack2(acc[i][j], lo, hi);
            float2 v; v.x = lo + bias; v.y = hi + bias;
            *(float2*)(out + base + n0 + tx * 4 + j * 2) = v;
        }
    }
}

// ---------------- launcher ---------------------------------------------------
extern "C" void kernel_launch(void* const* d_in, const int* in_sizes, int n_in,
                              void* d_out, int out_size) {
    const float* x     = (const float*)d_in[0];
    const float* bn1_g = (const float*)d_in[1];
    const float* bn1_b = (const float*)d_in[2];
    const float* w1    = (const float*)d_in[3];
    const float* b1    = (const float*)d_in[4];
    const float* bn2_g = (const float*)d_in[5];
    const float* bn2_b = (const float*)d_in[6];
    const float* w2    = (const float*)d_in[7];
    const float* b2    = (const float*)d_in[8];
    float* out = (float*)d_out;

    stats1_kernel<<<C1, 256>>>(x, bn1_g, bn1_b);
    fold1_kernel<<<C2, 256>>>(w1, b1);
    gemm1_kernel<<<dim3(T_ / 128, C2 / 128, B_), 256>>>(x);
    stats2_kernel<<<C2, 256>>>(bn2_g, bn2_b);
    fold2_kernel<<<C3, 256>>>(w2, b2);
    gemm2_kernel<<<dim3(T_ / 64, 1, B_), 256>>>(out);
}

// round 4
// speedup vs baseline: 2.1085x; 2.1085x over previous
#include <cuda_runtime.h>
#include <cuda_bf16.h>

#define B_   32
#define C1   1024
#define C2   256
#define C3   64
#define T_   2048
#define EPSV 1e-5f
#define MUHALF ((size_t)B_ * 32 * T_)
#define S1   8
#define S2   8

#define BM 128
#define BN 128
#define BK 32
#define KIT (C1 / BK)          /* 32 k-iterations */
#define G1_SMEM 65536          /* 2 buffers x 32KB */

typedef unsigned long long u64;
typedef unsigned int u32;

// ---------------- scratch (__device__ globals: allocation-free) --------------
__device__ float         g_h[(size_t)B_ * C2 * T_];        // 64 MB
__device__ __nv_bfloat16 g_w1h[C2 * C1], g_w1l[C2 * C1];
__device__ float g_b1f[C2];
__device__ float g_w2f[C3 * C2], g_b2f[C3];
__device__ float g_a1[C1], g_d1[C1], g_a2[C2], g_d2[C2];
__device__ float g_ps1[C1 * S1], g_pq1[C1 * S1];
__device__ float g_ps2[C2 * S2], g_pq2[C2 * S2];

// ---------------- helpers ------------------------------------------------------
__device__ __forceinline__ u32 smem_u32(const void* p) {
    u32 a; asm("{ .reg .u64 t; cvta.to.shared.u64 t, %1; cvt.u32.u64 %0, t; }" : "=r"(a) : "l"(p));
    return a;
}
__device__ __forceinline__ void ldsm4(u32* r, u32 addr) {
    asm volatile("ldmatrix.sync.aligned.m8n8.x4.shared.b16 {%0,%1,%2,%3}, [%4];"
        : "=r"(r[0]), "=r"(r[1]), "=r"(r[2]), "=r"(r[3]) : "r"(addr));
}
__device__ __forceinline__ void ldsm4t(u32* r, u32 addr) {
    asm volatile("ldmatrix.sync.aligned.m8n8.x4.trans.shared.b16 {%0,%1,%2,%3}, [%4];"
        : "=r"(r[0]), "=r"(r[1]), "=r"(r[2]), "=r"(r[3]) : "r"(addr));
}
__device__ __forceinline__ void mma16816(float* d, const u32* a, const u32* b) {
    asm volatile("mma.sync.aligned.m16n8k16.row.col.f32.bf16.bf16.f32 "
        "{%0,%1,%2,%3}, {%4,%5,%6,%7}, {%8,%9}, {%0,%1,%2,%3};"
        : "+f"(d[0]), "+f"(d[1]), "+f"(d[2]), "+f"(d[3])
        : "r"(a[0]), "r"(a[1]), "r"(a[2]), "r"(a[3]), "r"(b[0]), "r"(b[1]));
}
// split pair of f32 -> packed bf16x2 hi + packed bf16x2 lo (memory order: v0 low)
__device__ __forceinline__ void split2(float v0, float v1, u32& h, u32& l) {
    __nv_bfloat162 hh = __floats2bfloat162_rn(v0, v1);
    float r0 = v0 - __bfloat162float(hh.x);
    float r1 = v1 - __bfloat162float(hh.y);
    __nv_bfloat162 ll = __floats2bfloat162_rn(r0, r1);
    h = *(u32*)&hh; l = *(u32*)&ll;
}

// ---------------- f32x2 (gemm2) -------------------------------------------------
__device__ __forceinline__ u64 fma2(u64 a, u64 b, u64 c) {
    u64 r; asm("fma.rn.f32x2 %0, %1, %2, %3;" : "=l"(r) : "l"(a), "l"(b), "l"(c)); return r;
}
__device__ __forceinline__ u64 pack2(float x) {
    u64 r; asm("mov.b64 %0, {%1, %1};" : "=l"(r) : "f"(x)); return r;
}
__device__ __forceinline__ void unpack2(u64 p, float& lo, float& hi) {
    asm("mov.b64 {%0, %1}, %2;" : "=f"(lo), "=f"(hi) : "l"(p));
}

// ---------------- BN stats ------------------------------------------------------
__global__ void stats1_part_kernel(const float* __restrict__ x) {
    __shared__ float sh_s[256], sh_q[256];
    const int c = blockIdx.x, sp = blockIdx.y, tid = threadIdx.x;
    const int nb = B_ / S1;
    float s = 0.f, q = 0.f;
    for (int b = sp * nb; b < sp * nb + nb; b++) {
        const float4* row = (const float4*)(x + ((size_t)b * C1 + c) * T_);
        #pragma unroll
        for (int i = 0; i < T_ / 4 / 256; i++) {
            float4 v = row[tid + i * 256];
            s += v.x + v.y + v.z + v.w;
            q += v.x*v.x + v.y*v.y + v.z*v.z + v.w*v.w;
        }
    }
    sh_s[tid] = s; sh_q[tid] = q;
    __syncthreads();
    for (int off = 128; off > 0; off >>= 1) {
        if (tid < off) { sh_s[tid] += sh_s[tid + off]; sh_q[tid] += sh_q[tid + off]; }
        __syncthreads();
    }
    if (tid == 0) { g_ps1[c * S1 + sp] = sh_s[0]; g_pq1[c * S1 + sp] = sh_q[0]; }
}

__global__ void stats2_part_kernel() {
    __shared__ float sh_s[256], sh_q[256];
    const int c = blockIdx.x, sp = blockIdx.y, tid = threadIdx.x;
    const int nb = B_ / S2;
    float s = 0.f, q = 0.f;
    for (int b = sp * nb; b < sp * nb + nb; b++) {
        const float4* row = (const float4*)(g_h + ((size_t)b * C2 + c) * T_);
        #pragma unroll
        for (int i = 0; i < T_ / 4 / 256; i++) {
            float4 v = row[tid + i * 256];
            s += v.x + v.y + v.z + v.w;
            q += v.x*v.x + v.y*v.y + v.z*v.z + v.w*v.w;
        }
    }
    sh_s[tid] = s; sh_q[tid] = q;
    __syncthreads();
    for (int off = 128; off > 0; off >>= 1) {
        if (tid < off) { sh_s[tid] += sh_s[tid + off]; sh_q[tid] += sh_q[tid + off]; }
        __syncthreads();
    }
    if (tid == 0) { g_ps2[c * S2 + sp] = sh_s[0]; g_pq2[c * S2 + sp] = sh_q[0]; }
}

__global__ void finalize1_kernel(const float* __restrict__ g, const float* __restrict__ bt) {
    int c = blockIdx.x * 256 + threadIdx.x;
    if (c >= C1) return;
    float s = 0.f, q = 0.f;
    #pragma unroll
    for (int i = 0; i < S1; i++) { s += g_ps1[c * S1 + i]; q += g_pq1[c * S1 + i]; }
    const float inv_n = 1.f / (float)(B_ * T_);
    float mean = s * inv_n;
    float var  = q * inv_n - mean * mean;
    float av = g[c] * rsqrtf(var + EPSV);
    g_a1[c] = av;
    g_d1[c] = bt[c] - mean * av;
}

__global__ void finalize2_kernel(const float* __restrict__ g, const float* __restrict__ bt) {
    int c = threadIdx.x;
    if (c >= C2) return;
    float s = 0.f, q = 0.f;
    #pragma unroll
    for (int i = 0; i < S2; i++) { s += g_ps2[c * S2 + i]; q += g_pq2[c * S2 + i]; }
    const float inv_n = 1.f / (float)(B_ * T_);
    float mean = s * inv_n;
    float var  = q * inv_n - mean * mean;
    float av = g[c] * rsqrtf(var + EPSV);
    g_a2[c] = av;
    g_d2[c] = bt[c] - mean * av;
}

// ---------------- fold1: W1*a -> bf16 hi/lo, bias --------------------------------
__global__ void fold1_kernel(const float* __restrict__ w, const float* __restrict__ bias) {
    __shared__ float sh[256];
    const int o = blockIdx.x, tid = threadIdx.x;
    float acc = 0.f;
    for (int k = tid; k < C1; k += 256) {
        float wv = w[(size_t)o * C1 + k];
        float wf = wv * g_a1[k];
        __nv_bfloat16 h = __float2bfloat16(wf);
        g_w1h[(size_t)o * C1 + k] = h;
        g_w1l[(size_t)o * C1 + k] = __float2bfloat16(wf - __bfloat162float(h));
        acc += wv * g_d1[k];
    }
    sh[tid] = acc;
    __syncthreads();
    for (int off = 128; off > 0; off >>= 1) {
        if (tid < off) sh[tid] += sh[tid + off];
        __syncthreads();
    }
    if (tid == 0) g_b1f[o] = bias[o] + sh[0];
}

__global__ void fold2_kernel(const float* __restrict__ w, const float* __restrict__ bias) {
    __shared__ float sh[256];
    const int o = blockIdx.x, tid = threadIdx.x;
    float acc = 0.f;
    for (int k = tid; k < C2; k += 256) {
        float wv = w[(size_t)o * C2 + k];
        g_w2f[(size_t)o * C2 + k] = wv * g_a2[k];
        acc += wv * g_d2[k];
    }
    sh[tid] = acc;
    __syncthreads();
    for (int off = 128; off > 0; off >>= 1) {
        if (tid < off) sh[tid] += sh[tid + off];
        __syncthreads();
    }
    if (tid == 0) g_b2f[o] = bias[o] + sh[0];
}

// ---------------- GEMM1: mma.sync bf16 3-term, fused hi/lo split -----------------
// SMEM buffer layout (bytes, per 32KB stage): Ah@0, Al@8192, Bh@16384, Bl@24576
// A tiles [128m][32k] bf16, row 64B, chunk swizzle c^= (m>>1)&3
// B tiles [32k][128n] bf16, row 256B, chunk swizzle c^= k&7
extern __shared__ char g1s[];

__global__ __launch_bounds__(256) void gemm1_kernel(const float* __restrict__ x) {
    const int tid = threadIdx.x, lane = tid & 31, wid = tid >> 5;
    const int b = blockIdx.z, m0 = blockIdx.y * BM, n0 = blockIdx.x * BN;
    const int wm = (wid & 3) * 32, wn = (wid >> 2) * 64;

    // global-load assignments
    const int xrow = tid >> 3, xu = tid & 7;             // X: 32 rows x 8 thr, 16 floats each
    const int wm0 = tid >> 2,        wc0 = tid & 3;      // W uint4 idx tid
    const int wm1 = (tid + 256) >> 2, wc1 = tid & 3;     // W uint4 idx tid+256

    float xs[16];
    uint4 wsh0, wsh1, wsl0, wsl1;

    auto ldg = [&](int it) {
        const int k0 = it * BK;
        const float* xp = x + ((size_t)(b * C1 + k0 + xrow)) * T_ + n0 + xu * 16;
        #pragma unroll
        for (int j = 0; j < 4; j++) {
            float4 v = *(const float4*)(xp + j * 4);
            xs[j*4+0] = v.x; xs[j*4+1] = v.y; xs[j*4+2] = v.z; xs[j*4+3] = v.w;
        }
        const uint4* whp = (const uint4*)g_w1h;
        const uint4* wlp = (const uint4*)g_w1l;
        size_t o0 = (size_t)(m0 + wm0) * (C1/8) + (k0 >> 3) + wc0;
        size_t o1 = (size_t)(m0 + wm1) * (C1/8) + (k0 >> 3) + wc1;
        wsh0 = whp[o0]; wsh1 = whp[o1];
        wsl0 = wlp[o0]; wsl1 = wlp[o1];
    };

    auto sts = [&](int buf) {
        char* sb = g1s + buf * 32768;
        int p0 = (wc0 ^ ((wm0 >> 1) & 3)) * 16;
        int p1 = (wc1 ^ ((wm1 >> 1) & 3)) * 16;
        *(uint4*)(sb +        wm0 * 64 + p0) = wsh0;
        *(uint4*)(sb +        wm1 * 64 + p1) = wsh1;
        *(uint4*)(sb + 8192 + wm0 * 64 + p0) = wsl0;
        *(uint4*)(sb + 8192 + wm1 * 64 + p1) = wsl1;
        u32 h[4], l[4];
        split2(xs[0], xs[1], h[0], l[0]); split2(xs[2],  xs[3],  h[1], l[1]);
        split2(xs[4], xs[5], h[2], l[2]); split2(xs[6],  xs[7],  h[3], l[3]);
        int c0 = ((2 * xu) ^ (xrow & 7)) * 16;
        *(uint4*)(sb + 16384 + xrow * 256 + c0) = make_uint4(h[0], h[1], h[2], h[3]);
        *(uint4*)(sb + 24576 + xrow * 256 + c0) = make_uint4(l[0], l[1], l[2], l[3]);
        split2(xs[8],  xs[9],  h[0], l[0]); split2(xs[10], xs[11], h[1], l[1]);
        split2(xs[12], xs[13], h[2], l[2]); split2(xs[14], xs[15], h[3], l[3]);
        int c1 = ((2 * xu + 1) ^ (xrow & 7)) * 16;
        *(uint4*)(sb + 16384 + xrow * 256 + c1) = make_uint4(h[0], h[1], h[2], h[3]);
        *(uint4*)(sb + 24576 + xrow * 256 + c1) = make_uint4(l[0], l[1], l[2], l[3]);
    };

    float acc[2][8][4];
    #pragma unroll
    for (int mi = 0; mi < 2; mi++)
        #pragma unroll
        for (int nj = 0; nj < 8; nj++)
            #pragma unroll
            for (int r = 0; r < 4; r++) acc[mi][nj][r] = 0.f;

    ldg(0); sts(0);
    __syncthreads();

    for (int it = 0; it < KIT; it++) {
        if (it + 1 < KIT) ldg(it + 1);
        const u32 Abase = smem_u32(g1s + (it & 1) * 32768);
        #pragma unroll
        for (int ks = 0; ks < 2; ks++) {
            u32 ah[2][4], al[2][4];
            #pragma unroll
            for (int mi = 0; mi < 2; mi++) {
                int ml = wm + mi * 16 + (lane & 15);
                int kk = ks * 16 + (lane >> 4) * 8;
                u32 a_addr = Abase + ml * 64 + (((kk >> 3) ^ ((ml >> 1) & 3)) * 16);
                ldsm4(ah[mi], a_addr);
                ldsm4(al[mi], a_addr + 8192);
            }
            const int mat = lane >> 3, rr = lane & 7;
            #pragma unroll
            for (int nb = 0; nb < 4; nb++) {
                int kk = ks * 16 + (mat & 1) * 8 + rr;
                int nn = wn + nb * 16 + (mat >> 1) * 8;
                u32 b_addr = Abase + 16384 + kk * 256 + (((nn >> 3) ^ (kk & 7)) * 16);
                u32 bh[4], bl[4];
                ldsm4t(bh, b_addr);
                ldsm4t(bl, b_addr + 8192);
                #pragma unroll
                for (int mi = 0; mi < 2; mi++) {
                    mma16816(acc[mi][2*nb],     ah[mi], bh);
                    mma16816(acc[mi][2*nb],     ah[mi], bl);
                    mma16816(acc[mi][2*nb],     al[mi], bh);
                    mma16816(acc[mi][2*nb + 1], ah[mi], bh + 2);
                    mma16816(acc[mi][2*nb + 1], ah[mi], bl + 2);
                    mma16816(acc[mi][2*nb + 1], al[mi], bh + 2);
                }
            }
        }
        if (it + 1 < KIT) {
            sts((it + 1) & 1);
            __syncthreads();
        }
    }

    // epilogue: bias + relu -> g_h
    const int g = lane >> 2, q = lane & 3;
    #pragma unroll
    for (int mi = 0; mi < 2; mi++) {
        #pragma unroll
        for (int rw = 0; rw < 2; rw++) {
            const int m = m0 + wm + mi * 16 + g + rw * 8;
            const float bias = g_b1f[m];
            float* Hrow = g_h + ((size_t)b * C2 + m) * T_ + n0 + wn;
            #pragma unroll
            for (int nj = 0; nj < 8; nj++) {
                float2 v;
                v.x = fmaxf(acc[mi][nj][rw * 2 + 0] + bias, 0.f);
                v.y = fmaxf(acc[mi][nj][rw * 2 + 1] + bias, 0.f);
                *(float2*)(Hrow + nj * 8 + q * 2) = v;
            }
        }
    }
}

// ---------------- GEMM2 (f32x2): out = W2f @ h + b2f, split mu/logvar ------------
__global__ __launch_bounds__(256) void gemm2_kernel(float* __restrict__ out) {
    __shared__ float As[8][64];
    __shared__ float Bs[8][64];
    const int b  = blockIdx.z;
    const int n0 = blockIdx.x * 64;
    const int tid = threadIdx.x;
    const int tx = tid & 15, ty = tid >> 4;
    const float* H = g_h + (size_t)b * C2 * T_;

    u64 acc[4][2];
    #pragma unroll
    for (int i = 0; i < 4; i++) { acc[i][0] = 0ull; acc[i][1] = 0ull; }

    const int arow = tid >> 2, acol = (tid & 3) * 2;
    const int brow = tid >> 5, bcol = (tid & 31) * 2;

    for (int k0 = 0; k0 < C2; k0 += 8) {
        float2 av = *(const float2*)(g_w2f + (size_t)arow * C2 + k0 + acol);
        float2 bv = *(const float2*)(H + (size_t)(k0 + brow) * T_ + n0 + bcol);
        __syncthreads();
        As[acol + 0][arow] = av.x;
        As[acol + 1][arow] = av.y;
        *(float2*)&Bs[brow][bcol] = bv;
        __syncthreads();
        #pragma unroll
        for (int k = 0; k < 8; k++) {
            float4 a = *(const float4*)&As[k][ty * 4];
            const u64* bp = (const u64*)&Bs[k][tx * 4];
            u64 b0 = bp[0], b1 = bp[1];
            float ar[4] = {a.x, a.y, a.z, a.w};
            #pragma unroll
            for (int i = 0; i < 4; i++) {
                u64 A = pack2(ar[i]);
                acc[i][0] = fma2(A, b0, acc[i][0]);
                acc[i][1] = fma2(A, b1, acc[i][1]);
            }
        }
    }

    #pragma unroll
    for (int i = 0; i < 4; i++) {
        const int o = ty * 4 + i;
        const float bias = g_b2f[o];
        const size_t base = (o < 32)
            ? ((size_t)b * 32 * T_ + (size_t)o * T_)
            : (MUHALF + (size_t)b * 32 * T_ + (size_t)(o - 32) * T_);
        #pragma unroll
        for (int j = 0; j < 2; j++) {
            float lo, hi; unpack2(acc[i][j], lo, hi);
            float2 v; v.x = lo + bias; v.y = hi + bias;
            *(float2*)(out + base + n0 + tx * 4 + j * 2) = v;
        }
    }
}

// ---------------- launcher --------------------------------------------------------
extern "C" void kernel_launch(void* const* d_in, const int* in_sizes, int n_in,
                              void* d_out, int out_size) {
    const float* x     = (const float*)d_in[0];
    const float* bn1_g = (const float*)d_in[1];
    const float* bn1_b = (const float*)d_in[2];
    const float* w1    = (const float*)d_in[3];
    const float* b1    = (const float*)d_in[4];
    const float* bn2_g = (const float*)d_in[5];
    const float* bn2_b = (const float*)d_in[6];
    const float* w2    = (const float*)d_in[7];
    const float* b2    = (const float*)d_in[8];
    float* out = (float*)d_out;

    cudaFuncSetAttribute(gemm1_kernel, cudaFuncAttributeMaxDynamicSharedMemorySize, G1_SMEM);

    stats1_part_kernel<<<dim3(C1, S1), 256>>>(x);
    finalize1_kernel<<<(C1 + 255) / 256, 256>>>(bn1_g, bn1_b);
    fold1_kernel<<<C2, 256>>>(w1, b1);
    gemm1_kernel<<<dim3(T_ / BN, C2 / BM, B_), 256, G1_SMEM>>>(x);
    stats2_part_kernel<<<dim3(C2, S2), 256>>>();
    finalize2_kernel<<<1, 256>>>(bn2_g, bn2_b);
    fold2_kernel<<<C3, 256>>>(w2, b2);
    gemm2_kernel<<<dim3(T_ / 64, 1, B_), 256>>>(out);
}

// round 5
// speedup vs baseline: 2.6471x; 1.2554x over previous
#include <cuda_runtime.h>
#include <cuda_bf16.h>

#define B_   32
#define C1   1024
#define C2   256
#define C3   64
#define T_   2048
#define EPSV 1e-5f
#define MUHALF ((size_t)B_ * 32 * T_)
#define S1   8
#define S2   8

#define BM 128
#define BN 128
#define BK 32
#define KIT  (C1 / BK)          /* 32 */
#define KIT2 (C2 / BK)          /* 8  */
#define G1_STAGE 32768
#define G1_SMEM  (3 * G1_STAGE) /* 96KB, 3-stage ring */
#define G2_STAGE 24576
#define G2_SMEM  (2 * G2_STAGE) /* 48KB */

typedef unsigned long long u64;
typedef unsigned int u32;

// ---------------- scratch (__device__ globals: allocation-free) --------------
__device__ __nv_bfloat16 g_xh[(size_t)B_ * C1 * T_];   // 128 MB  X hi (same layout as x)
__device__ __nv_bfloat16 g_xl[(size_t)B_ * C1 * T_];   // 128 MB  X lo
__device__ u32 g_hh[(size_t)B_ * C2 * T_ / 2];          // 32 MB   h hi (bf16x2 packed)
__device__ u32 g_hl[(size_t)B_ * C2 * T_ / 2];          // 32 MB   h lo
__device__ __nv_bfloat16 g_w1h[C2 * C1], g_w1l[C2 * C1];
__device__ __nv_bfloat16 g_w2h[C3 * C2], g_w2l[C3 * C2];
__device__ float g_b1f[C2], g_b2f[C3];
__device__ float g_a1[C1], g_d1[C1], g_a2[C2], g_d2[C2];
__device__ float g_ps1[C1 * S1], g_pq1[C1 * S1];
__device__ float g_ps2[C2 * S2], g_pq2[C2 * S2];

// ---------------- helpers ------------------------------------------------------
__device__ __forceinline__ u32 smem_u32(const void* p) {
    u32 a; asm("{ .reg .u64 t; cvta.to.shared.u64 t, %1; cvt.u32.u64 %0, t; }" : "=r"(a) : "l"(p));
    return a;
}
__device__ __forceinline__ void cp16(u32 dst, const void* src) {
    asm volatile("cp.async.cg.shared.global [%0], [%1], 16;" :: "r"(dst), "l"(src));
}
__device__ __forceinline__ void cpcommit() { asm volatile("cp.async.commit_group;" ::: "memory"); }
__device__ __forceinline__ void cpwait(int rem) {
    if (rem >= 2)      asm volatile("cp.async.wait_group 2;" ::: "memory");
    else if (rem == 1) asm volatile("cp.async.wait_group 1;" ::: "memory");
    else               asm volatile("cp.async.wait_group 0;" ::: "memory");
}
__device__ __forceinline__ void ldsm4(u32* r, u32 addr) {
    asm volatile("ldmatrix.sync.aligned.m8n8.x4.shared.b16 {%0,%1,%2,%3}, [%4];"
        : "=r"(r[0]), "=r"(r[1]), "=r"(r[2]), "=r"(r[3]) : "r"(addr));
}
__device__ __forceinline__ void ldsm4t(u32* r, u32 addr) {
    asm volatile("ldmatrix.sync.aligned.m8n8.x4.trans.shared.b16 {%0,%1,%2,%3}, [%4];"
        : "=r"(r[0]), "=r"(r[1]), "=r"(r[2]), "=r"(r[3]) : "r"(addr));
}
__device__ __forceinline__ void mma16816(float* d, const u32* a, const u32* b) {
    asm volatile("mma.sync.aligned.m16n8k16.row.col.f32.bf16.bf16.f32 "
        "{%0,%1,%2,%3}, {%4,%5,%6,%7}, {%8,%9}, {%0,%1,%2,%3};"
        : "+f"(d[0]), "+f"(d[1]), "+f"(d[2]), "+f"(d[3])
        : "r"(a[0]), "r"(a[1]), "r"(a[2]), "r"(a[3]), "r"(b[0]), "r"(b[1]));
}
__device__ __forceinline__ void split2(float v0, float v1, u32& h, u32& l) {
    __nv_bfloat162 hh = __floats2bfloat162_rn(v0, v1);
    float r0 = v0 - __bfloat162float(hh.x);
    float r1 = v1 - __bfloat162float(hh.y);
    __nv_bfloat162 ll = __floats2bfloat162_rn(r0, r1);
    h = *(u32*)&hh; l = *(u32*)&ll;
}

// ---------------- stats1 fused with X hi/lo split --------------------------------
__global__ __launch_bounds__(256) void stats1_split_kernel(const float* __restrict__ x) {
    __shared__ float sh_s[256], sh_q[256];
    const int c = blockIdx.x, sp = blockIdx.y, tid = threadIdx.x;
    float4 v[8];
    #pragma unroll
    for (int j = 0; j < 8; j++) {
        int b = sp * 4 + (j >> 1);
        int i = j & 1;
        v[j] = ((const float4*)(x + ((size_t)b * C1 + c) * T_))[tid + i * 256];
    }
    float s = 0.f, q = 0.f;
    #pragma unroll
    for (int j = 0; j < 8; j++) {
        s += v[j].x + v[j].y + v[j].z + v[j].w;
        q += v[j].x*v[j].x + v[j].y*v[j].y + v[j].z*v[j].z + v[j].w*v[j].w;
        int b = sp * 4 + (j >> 1);
        int i = j & 1;
        u32 h0, l0, h1, l1;
        split2(v[j].x, v[j].y, h0, l0);
        split2(v[j].z, v[j].w, h1, l1);
        size_t rowoff = ((size_t)b * C1 + c) * T_;
        *(uint2*)((u32*)(g_xh + rowoff) + (tid + i * 256) * 2) = make_uint2(h0, h1);
        *(uint2*)((u32*)(g_xl + rowoff) + (tid + i * 256) * 2) = make_uint2(l0, l1);
    }
    sh_s[tid] = s; sh_q[tid] = q;
    __syncthreads();
    for (int off = 128; off > 0; off >>= 1) {
        if (tid < off) { sh_s[tid] += sh_s[tid + off]; sh_q[tid] += sh_q[tid + off]; }
        __syncthreads();
    }
    if (tid == 0) { g_ps1[c * S1 + sp] = sh_s[0]; g_pq1[c * S1 + sp] = sh_q[0]; }
}

// ---------------- stats2 on hh/hl --------------------------------------------------
__global__ __launch_bounds__(256) void stats2_part_kernel() {
    __shared__ float sh_s[256], sh_q[256];
    const int c = blockIdx.x, sp = blockIdx.y, tid = threadIdx.x;
    uint4 H[4], L[4];
    #pragma unroll
    for (int j = 0; j < 4; j++) {
        int b = sp * 4 + j;
        size_t rowq = ((size_t)b * C2 + c) * T_ / 8;   // uint4 index
        H[j] = ((const uint4*)g_hh)[rowq + tid];
        L[j] = ((const uint4*)g_hl)[rowq + tid];
    }
    float s = 0.f, q = 0.f;
    #pragma unroll
    for (int j = 0; j < 4; j++) {
        u32 hw[4] = {H[j].x, H[j].y, H[j].z, H[j].w};
        u32 lw[4] = {L[j].x, L[j].y, L[j].z, L[j].w};
        #pragma unroll
        for (int k = 0; k < 4; k++) {
            __nv_bfloat162 hb = *(__nv_bfloat162*)&hw[k];
            __nv_bfloat162 lb = *(__nv_bfloat162*)&lw[k];
            float v0 = __bfloat162float(hb.x) + __bfloat162float(lb.x);
            float v1 = __bfloat162float(hb.y) + __bfloat162float(lb.y);
            s += v0 + v1;
            q += v0 * v0 + v1 * v1;
        }
    }
    sh_s[tid] = s; sh_q[tid] = q;
    __syncthreads();
    for (int off = 128; off > 0; off >>= 1) {
        if (tid < off) { sh_s[tid] += sh_s[tid + off]; sh_q[tid] += sh_q[tid + off]; }
        __syncthreads();
    }
    if (tid == 0) { g_ps2[c * S2 + sp] = sh_s[0]; g_pq2[c * S2 + sp] = sh_q[0]; }
}

__global__ void finalize1_kernel(const float* __restrict__ g, const float* __restrict__ bt) {
    int c = blockIdx.x * 256 + threadIdx.x;
    if (c >= C1) return;
    float s = 0.f, q = 0.f;
    #pragma unroll
    for (int i = 0; i < S1; i++) { s += g_ps1[c * S1 + i]; q += g_pq1[c * S1 + i]; }
    const float inv_n = 1.f / (float)(B_ * T_);
    float mean = s * inv_n;
    float var  = q * inv_n - mean * mean;
    float av = g[c] * rsqrtf(var + EPSV);
    g_a1[c] = av;
    g_d1[c] = bt[c] - mean * av;
}

__global__ void finalize2_kernel(const float* __restrict__ g, const float* __restrict__ bt) {
    int c = threadIdx.x;
    if (c >= C2) return;
    float s = 0.f, q = 0.f;
    #pragma unroll
    for (int i = 0; i < S2; i++) { s += g_ps2[c * S2 + i]; q += g_pq2[c * S2 + i]; }
    const float inv_n = 1.f / (float)(B_ * T_);
    float mean = s * inv_n;
    float var  = q * inv_n - mean * mean;
    float av = g[c] * rsqrtf(var + EPSV);
    g_a2[c] = av;
    g_d2[c] = bt[c] - mean * av;
}

// ---------------- folds ---------------------------------------------------------
__global__ void fold1_kernel(const float* __restrict__ w, const float* __restrict__ bias) {
    __shared__ float sh[256];
    const int o = blockIdx.x, tid = threadIdx.x;
    float acc = 0.f;
    for (int k = tid; k < C1; k += 256) {
        float wv = w[(size_t)o * C1 + k];
        float wf = wv * g_a1[k];
        __nv_bfloat16 h = __float2bfloat16(wf);
        g_w1h[(size_t)o * C1 + k] = h;
        g_w1l[(size_t)o * C1 + k] = __float2bfloat16(wf - __bfloat162float(h));
        acc += wv * g_d1[k];
    }
    sh[tid] = acc;
    __syncthreads();
    for (int off = 128; off > 0; off >>= 1) {
        if (tid < off) sh[tid] += sh[tid + off];
        __syncthreads();
    }
    if (tid == 0) g_b1f[o] = bias[o] + sh[0];
}

__global__ void fold2_kernel(const float* __restrict__ w, const float* __restrict__ bias) {
    __shared__ float sh[256];
    const int o = blockIdx.x, tid = threadIdx.x;
    float acc = 0.f;
    for (int k = tid; k < C2; k += 256) {
        float wv = w[(size_t)o * C2 + k];
        float wf = wv * g_a2[k];
        __nv_bfloat16 h = __float2bfloat16(wf);
        g_w2h[(size_t)o * C2 + k] = h;
        g_w2l[(size_t)o * C2 + k] = __float2bfloat16(wf - __bfloat162float(h));
        acc += wv * g_d2[k];
    }
    sh[tid] = acc;
    __syncthreads();
    for (int off = 128; off > 0; off >>= 1) {
        if (tid < off) sh[tid] += sh[tid + off];
        __syncthreads();
    }
    if (tid == 0) g_b2f[o] = bias[o] + sh[0];
}

// ---------------- GEMM1: cp.async 3-stage, mma bf16 3-term ------------------------
// Stage layout (32KB): Ah[0,8K) Al[8K,16K) Bh[16K,24K) Bl[24K,32K)
extern __shared__ char g1s[];

__device__ __forceinline__ void g1_issue(u32 sb, int it, int m0, int n0, int b, int tid) {
    const int k0 = it * BK;
    #pragma unroll
    for (int j = 0; j < 2; j++) {           // A: 512 uint4 (8KB) each h/l
        int u = tid + j * 256;
        int row = u >> 2, c = u & 3;
        u32 dst = sb + row * 64 + ((c ^ ((row >> 1) & 3)) << 4);
        size_t src = (size_t)(m0 + row) * (C1 / 8) + (k0 >> 3) + c;
        cp16(dst,        (const uint4*)g_w1h + src);
        cp16(dst + 8192, (const uint4*)g_w1l + src);
    }
    #pragma unroll
    for (int j = 0; j < 2; j++) {           // B: 512 uint4 (8KB) each h/l
        int u = tid + j * 256;
        int row = u >> 4, c = u & 15;
        u32 dst = sb + 16384 + row * 256 + ((c ^ (row & 7)) << 4);
        size_t src = (((size_t)(b * C1 + k0 + row)) * T_ + n0) / 8 + c;
        cp16(dst,        (const uint4*)g_xh + src);
        cp16(dst + 8192, (const uint4*)g_xl + src);
    }
    cpcommit();
}

__global__ __launch_bounds__(256, 2) void gemm1_kernel() {
    const int tid = threadIdx.x, lane = tid & 31, wid = tid >> 5;
    const int b = blockIdx.z, m0 = blockIdx.y * BM, n0 = blockIdx.x * BN;
    const int wm = (wid & 3) * 32, wn = (wid >> 2) * 64;
    const u32 sb0 = smem_u32(g1s);

    float acc[2][8][4];
    #pragma unroll
    for (int mi = 0; mi < 2; mi++)
        #pragma unroll
        for (int nj = 0; nj < 8; nj++)
            #pragma unroll
            for (int r = 0; r < 4; r++) acc[mi][nj][r] = 0.f;

    #pragma unroll
    for (int s = 0; s < 3; s++) g1_issue(sb0 + s * G1_STAGE, s, m0, n0, b, tid);

    for (int it = 0; it < KIT; it++) {
        cpwait(KIT - 1 - it);
        __syncthreads();
        const u32 Abase = sb0 + (it % 3) * G1_STAGE;
        #pragma unroll
        for (int ks = 0; ks < 2; ks++) {
            u32 ah[2][4], al[2][4];
            #pragma unroll
            for (int mi = 0; mi < 2; mi++) {
                int ml = wm + mi * 16 + (lane & 15);
                int kk = ks * 16 + (lane >> 4) * 8;
                u32 a_addr = Abase + ml * 64 + (((kk >> 3) ^ ((ml >> 1) & 3)) << 4);
                ldsm4(ah[mi], a_addr);
                ldsm4(al[mi], a_addr + 8192);
            }
            const int mat = lane >> 3, rr = lane & 7;
            #pragma unroll
            for (int nb = 0; nb < 4; nb++) {
                int kk = ks * 16 + (mat & 1) * 8 + rr;
                int nn = wn + nb * 16 + (mat >> 1) * 8;
                u32 b_addr = Abase + 16384 + kk * 256 + (((nn >> 3) ^ (kk & 7)) << 4);
                u32 bh[4], bl[4];
                ldsm4t(bh, b_addr);
                ldsm4t(bl, b_addr + 8192);
                #pragma unroll
                for (int mi = 0; mi < 2; mi++) {
                    mma16816(acc[mi][2*nb],     ah[mi], bh);
                    mma16816(acc[mi][2*nb],     ah[mi], bl);
                    mma16816(acc[mi][2*nb],     al[mi], bh);
                    mma16816(acc[mi][2*nb + 1], ah[mi], bh + 2);
                    mma16816(acc[mi][2*nb + 1], ah[mi], bl + 2);
                    mma16816(acc[mi][2*nb + 1], al[mi], bh + 2);
                }
            }
        }
        __syncthreads();
        if (it + 3 < KIT) g1_issue(Abase, it + 3, m0, n0, b, tid);
    }

    // epilogue: v = relu(acc + bias); split -> g_hh / g_hl (bf16x2 per u32)
    const int g = lane >> 2, q = lane & 3;
    #pragma unroll
    for (int mi = 0; mi < 2; mi++) {
        #pragma unroll
        for (int rw = 0; rw < 2; rw++) {
            const int m = m0 + wm + mi * 16 + g + rw * 8;
            const float bias = g_b1f[m];
            size_t rowu = (((size_t)b * C2 + m) * T_ + n0 + wn) / 2;  // u32 index
            #pragma unroll
            for (int nj = 0; nj < 8; nj++) {
                float v0 = fmaxf(acc[mi][nj][rw * 2 + 0] + bias, 0.f);
                float v1 = fmaxf(acc[mi][nj][rw * 2 + 1] + bias, 0.f);
                u32 h, l;
                split2(v0, v1, h, l);
                g_hh[rowu + nj * 4 + q] = h;
                g_hl[rowu + nj * 4 + q] = l;
            }
        }
    }
}

// ---------------- GEMM2: cp.async 2-stage, mma bf16 3-term ------------------------
// Stage layout (24KB): Ah[0,4K) Al[4K,8K) Bh[8K,16K) Bl[16K,24K)
extern __shared__ char g2s[];

__device__ __forceinline__ void g2_issue(u32 sb, int it, int n0, int b, int tid) {
    const int k0 = it * BK;
    {   // A: 256 uint4 (4KB) each h/l
        int row = tid >> 2, c = tid & 3;
        u32 dst = sb + row * 64 + ((c ^ ((row >> 1) & 3)) << 4);
        size_t src = (size_t)row * (C2 / 8) + (k0 >> 3) + c;
        cp16(dst,        (const uint4*)g_w2h + src);
        cp16(dst + 4096, (const uint4*)g_w2l + src);
    }
    #pragma unroll
    for (int j = 0; j < 2; j++) {   // B: 512 uint4 (8KB) each h/l
        int u = tid + j * 256;
        int row = u >> 4, c = u & 15;
        u32 dst = sb + 8192 + row * 256 + ((c ^ (row & 7)) << 4);
        size_t src = (((size_t)(b * C2 + k0 + row)) * T_ + n0) / 8 + c;
        cp16(dst,        (const uint4*)g_hh + src);
        cp16(dst + 8192, (const uint4*)g_hl + src);
    }
    cpcommit();
}

__global__ __launch_bounds__(256) void gemm2_kernel(float* __restrict__ out) {
    const int tid = threadIdx.x, lane = tid & 31, wid = tid >> 5;
    const int b = blockIdx.z, n0 = blockIdx.x * 128;
    const int wm = (wid & 1) * 32, wn = (wid >> 1) * 32;
    const u32 sb0 = smem_u32(g2s);

    float acc[2][4][4];
    #pragma unroll
    for (int mi = 0; mi < 2; mi++)
        #pragma unroll
        for (int nj = 0; nj < 4; nj++)
            #pragma unroll
            for (int r = 0; r < 4; r++) acc[mi][nj][r] = 0.f;

    g2_issue(sb0, 0, n0, b, tid);

    for (int it = 0; it < KIT2; it++) {
        if (it + 1 < KIT2) g2_issue(sb0 + ((it + 1) & 1) * G2_STAGE, it + 1, n0, b, tid);
        if (it + 1 < KIT2) asm volatile("cp.async.wait_group 1;" ::: "memory");
        else               asm volatile("cp.async.wait_group 0;" ::: "memory");
        __syncthreads();
        const u32 Bbase = sb0 + (it & 1) * G2_STAGE;
        #pragma unroll
        for (int ks = 0; ks < 2; ks++) {
            u32 ah[2][4], al[2][4];
            #pragma unroll
            for (int mi = 0; mi < 2; mi++) {
                int ml = wm + mi * 16 + (lane & 15);
                int kk = ks * 16 + (lane >> 4) * 8;
                u32 a_addr = Bbase + ml * 64 + (((kk >> 3) ^ ((ml >> 1) & 3)) << 4);
                ldsm4(ah[mi], a_addr);
                ldsm4(al[mi], a_addr + 4096);
            }
            const int mat = lane >> 3, rr = lane & 7;
            #pragma unroll
            for (int nbk = 0; nbk < 2; nbk++) {
                int kk = ks * 16 + (mat & 1) * 8 + rr;
                int nn = wn + nbk * 16 + (mat >> 1) * 8;
                u32 b_addr = Bbase + 8192 + kk * 256 + (((nn >> 3) ^ (kk & 7)) << 4);
                u32 bh[4], bl[4];
                ldsm4t(bh, b_addr);
                ldsm4t(bl, b_addr + 8192);
                #pragma unroll
                for (int mi = 0; mi < 2; mi++) {
                    mma16816(acc[mi][2*nbk],     ah[mi], bh);
                    mma16816(acc[mi][2*nbk],     ah[mi], bl);
                    mma16816(acc[mi][2*nbk],     al[mi], bh);
                    mma16816(acc[mi][2*nbk + 1], ah[mi], bh + 2);
                    mma16816(acc[mi][2*nbk + 1], ah[mi], bl + 2);
                    mma16816(acc[mi][2*nbk + 1], al[mi], bh + 2);
                }
            }
        }
        __syncthreads();
    }

    // epilogue: bias + mu/logvar split
    const int g = lane >> 2, q = lane & 3;
    #pragma unroll
    for (int mi = 0; mi < 2; mi++) {
        #pragma unroll
        for (int rw = 0; rw < 2; rw++) {
            const int o = wm + mi * 16 + g + rw * 8;
            const float bias = g_b2f[o];
            const size_t base = (o < 32)
                ? ((size_t)b * 32 * T_ + (size_t)o * T_)
                : (MUHALF + (size_t)b * 32 * T_ + (size_t)(o - 32) * T_);
            #pragma unroll
            for (int nj = 0; nj < 4; nj++) {
                float2 v;
                v.x = acc[mi][nj][rw * 2 + 0] + bias;
                v.y = acc[mi][nj][rw * 2 + 1] + bias;
                *(float2*)(out + base + n0 + wn + nj * 8 + q * 2) = v;
            }
        }
    }
}

// ---------------- launcher --------------------------------------------------------
extern "C" void kernel_launch(void* const* d_in, const int* in_sizes, int n_in,
                              void* d_out, int out_size) {
    const float* x     = (const float*)d_in[0];
    const float* bn1_g = (const float*)d_in[1];
    const float* bn1_b = (const float*)d_in[2];
    const float* w1    = (const float*)d_in[3];
    const float* b1    = (const float*)d_in[4];
    const float* bn2_g = (const float*)d_in[5];
    const float* bn2_b = (const float*)d_in[6];
    const float* w2    = (const float*)d_in[7];
    const float* b2    = (const float*)d_in[8];
    float* out = (float*)d_out;

    cudaFuncSetAttribute(gemm1_kernel, cudaFuncAttributeMaxDynamicSharedMemorySize, G1_SMEM);
    cudaFuncSetAttribute(gemm2_kernel, cudaFuncAttributeMaxDynamicSharedMemorySize, G2_SMEM);

    stats1_split_kernel<<<dim3(C1, S1), 256>>>(x);
    finalize1_kernel<<<(C1 + 255) / 256, 256>>>(bn1_g, bn1_b);
    fold1_kernel<<<C2, 256>>>(w1, b1);
    gemm1_kernel<<<dim3(T_ / BN, C2 / BM, B_), 256, G1_SMEM>>>();
    stats2_part_kernel<<<dim3(C2, S2), 256>>>();
    finalize2_kernel<<<1, 256>>>(bn2_g, bn2_b);
    fold2_kernel<<<C3, 256>>>(w2, b2);
    gemm2_kernel<<<dim3(T_ / 128, 1, B_), 256, G2_SMEM>>>(out);
}